// round 16
// baseline (speedup 1.0000x reference)
#include <cuda_runtime.h>
#include <cuda_bf16.h>
#include <cstdint>

// Problem constants
#define N_ROWS 16384
#define D_IN   1024
#define D_OUT  512
#define N_EXP  8
#define NPAD   (N_ROWS + N_EXP * 128)   // 17408

// GEMM tiling: 128x64 CTA tile, 8 warps of 32x32, 2 CTAs/SM
#define BM 128
#define BN 64
#define KC 32
#define NCHUNK (D_IN / KC)              // 32
#define NSTAGE 6
#define NTHREADS 256
#define MAX_TILES (N_ROWS / 128 + N_EXP) // 136

// SMEM stage: X0(4K) | X1(4K) | W0(2K) | W1(2K) = 12KB/stage
#define STG 12288
#define SMEM_TOTAL (NSTAGE * STG)       // 73728

// ---------------- device scratch ------------------------------------------
__device__ int g_cur[N_EXP];
__device__ int g_off[N_EXP + 1];
__device__ int g_end[N_EXP];
__device__ int g_perm[NPAD];
__device__ int g_tile_e[MAX_TILES];
__device__ int g_tile_r[MAX_TILES];
__device__ uint8_t g_x0c[(size_t)NCHUNK * NPAD * 32];
__device__ uint8_t g_x1c[(size_t)NCHUNK * NPAD * 32];
__device__ uint8_t g_w0c[(size_t)N_EXP * NCHUNK * D_OUT * 32];
__device__ uint8_t g_w1c[(size_t)N_EXP * NCHUNK * D_OUT * 32];
__device__ float   g_invqx[NPAD];
__device__ float   g_invqw[N_EXP * D_OUT];

// ---------------- PTX helpers ----------------------------------------------
__device__ __forceinline__ uint32_t smem_u32(const void* p) {
    uint32_t a;
    asm("{ .reg .u64 t; cvta.to.shared.u64 t, %1; cvt.u32.u64 %0, t; }" : "=r"(a) : "l"(p));
    return a;
}
#define MBARRIER_INIT(a, n) \
    asm volatile("mbarrier.init.shared.b64 [%0], %1;" :: "r"((uint32_t)(a)), "r"((uint32_t)(n)) : "memory")
#define MBARRIER_EXPECT_TX(a, tx) \
    asm volatile("mbarrier.arrive.expect_tx.shared.b64 _, [%0], %1;" :: "r"((uint32_t)(a)), "r"((uint32_t)(tx)) : "memory")
#define MBARRIER_WAIT_PARITY(a, ph) do { \
    uint32_t _m = (uint32_t)(a); uint32_t _p = (uint32_t)(ph); uint32_t _d; \
    asm volatile("{ .reg .pred p; mbarrier.try_wait.parity.acquire.cta.shared::cta.b64 p, [%1], %2; selp.b32 %0, 1, 0, p; }" \
        : "=r"(_d) : "r"(_m), "r"(_p) : "memory"); \
    if (!_d) { \
        asm volatile("{ .reg .pred P1; WL_%=: mbarrier.try_wait.parity.acquire.cta.shared::cta.b64 P1, [%0], %1, 0x989680; @P1 bra.uni WD_%=; bra.uni WL_%=; WD_%=: }" \
            :: "r"(_m), "r"(_p) : "memory"); \
    } } while (0)
__device__ __forceinline__ void bulk_g2s(uint32_t dst, const void* src, uint32_t bytes, uint32_t mbar) {
    asm volatile("cp.async.bulk.shared::cluster.global.mbarrier::complete_tx::bytes [%0], [%1], %2, [%3];"
                 :: "r"(dst), "l"(src), "r"(bytes), "r"(mbar) : "memory");
}
__device__ __forceinline__ void ldsm4(uint32_t* r, uint32_t a) {
    asm volatile("ldmatrix.sync.aligned.m8n8.x4.shared.b16 {%0,%1,%2,%3}, [%4];"
                 : "=r"(r[0]), "=r"(r[1]), "=r"(r[2]), "=r"(r[3]) : "r"(a));
}
__device__ __forceinline__ void mma_s8(int* c, const uint32_t* a, uint32_t b0, uint32_t b1) {
    asm volatile("mma.sync.aligned.m16n8k32.row.col.s32.s8.s8.s32 "
                 "{%0,%1,%2,%3}, {%4,%5,%6,%7}, {%8,%9}, {%0,%1,%2,%3};"
                 : "+r"(c[0]), "+r"(c[1]), "+r"(c[2]), "+r"(c[3])
                 : "r"(a[0]), "r"(a[1]), "r"(a[2]), "r"(a[3]), "r"(b0), "r"(b1));
}

// ---------------- bucketing: fused histogram + scan -------------------------
__global__ void k_hist_scan(const int* __restrict__ idx) {
    const int t = threadIdx.x;
    int cnt[N_EXP];
    #pragma unroll
    for (int k = 0; k < N_EXP; ++k) cnt[k] = 0;
    for (int i = t; i < N_ROWS; i += 1024) {
        const int e = idx[i];
        #pragma unroll
        for (int k = 0; k < N_EXP; ++k) cnt[k] += (e == k);
    }
    #pragma unroll
    for (int k = 0; k < N_EXP; ++k)
        #pragma unroll
        for (int o = 16; o > 0; o >>= 1)
            cnt[k] += __shfl_xor_sync(0xffffffffu, cnt[k], o);
    __shared__ int acc[N_EXP];
    if (t < N_EXP) { acc[t] = 0; g_cur[t] = 0; }
    __syncthreads();
    if ((t & 31) == 0)
        #pragma unroll
        for (int k = 0; k < N_EXP; ++k) atomicAdd(&acc[k], cnt[k]);
    __syncthreads();
    if (t == 0) {
        int off = 0, tt = 0;
        for (int e = 0; e < N_EXP; ++e) {
            g_off[e] = off;
            const int c = acc[e];
            for (int r = 0; r < c; r += 128) { g_tile_e[tt] = e; g_tile_r[tt] = off + r; ++tt; }
            g_end[e] = off + c;
            off += (c + 127) & ~127;
        }
        g_off[N_EXP] = off;
        for (; tt < MAX_TILES; ++tt) g_tile_e[tt] = -1;
    }
}
__global__ void k_scatter(const int* __restrict__ idx) {
    __shared__ int loc[N_EXP], base[N_EXP];
    const int tid = threadIdx.x;
    if (tid < N_EXP) loc[tid] = 0;
    __syncthreads();
    const int i = blockIdx.x * 256 + tid;
    const int e = idx[i];
    const int r = atomicAdd(&loc[e], 1);
    __syncthreads();
    if (tid < N_EXP) base[tid] = atomicAdd(&g_cur[tid], loc[tid]);
    __syncthreads();
    g_perm[g_off[e] + base[e] + r] = i;
}

// ---------------- warp-per-row int8 two-stream quantization -----------------
// One warp owns one row; lane l owns elements [32l, 32l+32) = chunk l's 32B.
__device__ __forceinline__ void quant_row_warp(const float* __restrict__ srcrow,
                                               uint8_t* __restrict__ d0base,  // + chunk*stride
                                               uint8_t* __restrict__ d1base,
                                               size_t chunk_stride, int slot_in_chunk,
                                               int swz, float* __restrict__ invq_out) {
    const int l = threadIdx.x & 31;
    float4 v[8];
    #pragma unroll
    for (int i = 0; i < 8; ++i) v[i] = ((const float4*)srcrow)[l * 8 + i];
    float m = 0.f;
    #pragma unroll
    for (int i = 0; i < 8; ++i) {
        m = fmaxf(m, fmaxf(fmaxf(fabsf(v[i].x), fabsf(v[i].y)),
                           fmaxf(fabsf(v[i].z), fabsf(v[i].w))));
    }
    #pragma unroll
    for (int o = 16; o > 0; o >>= 1) m = fmaxf(m, __shfl_xor_sync(0xffffffffu, m, o));
    const float maxv = fmaxf(m, 1e-30f);
    const float q128 = 16256.f / maxv;
    uint32_t c0[8], c1[8];
    #pragma unroll
    for (int i = 0; i < 8; ++i) {
        float f[4] = {v[i].x, v[i].y, v[i].z, v[i].w};
        int x0[4], x1[4];
        #pragma unroll
        for (int k = 0; k < 4; ++k) {
            const int full = __float2int_rn(f[k] * q128);
            x0[k] = (full + 64) >> 7;
            x1[k] = full - (x0[k] << 7);
        }
        c0[i] = __byte_perm(__byte_perm(x0[0], x0[1], 0x0040),
                            __byte_perm(x0[2], x0[3], 0x0040), 0x5410);
        c1[i] = __byte_perm(__byte_perm(x1[0], x1[1], 0x0040),
                            __byte_perm(x1[2], x1[3], 0x0040), 0x5410);
    }
    // chunk l segment = 32B; halves swapped when swz set
    uint8_t* p0 = d0base + (size_t)l * chunk_stride + (size_t)slot_in_chunk * 32;
    uint8_t* p1 = d1base + (size_t)l * chunk_stride + (size_t)slot_in_chunk * 32;
    uint4 h0 = make_uint4(c0[0], c0[1], c0[2], c0[3]);
    uint4 h1 = make_uint4(c0[4], c0[5], c0[6], c0[7]);
    uint4 g0 = make_uint4(c1[0], c1[1], c1[2], c1[3]);
    uint4 g1 = make_uint4(c1[4], c1[5], c1[6], c1[7]);
    if (swz) {
        *(uint4*)(p0)      = h1; *(uint4*)(p0 + 16) = h0;
        *(uint4*)(p1)      = g1; *(uint4*)(p1 + 16) = g0;
    } else {
        *(uint4*)(p0)      = h0; *(uint4*)(p0 + 16) = h1;
        *(uint4*)(p1)      = g0; *(uint4*)(p1 + 16) = g1;
    }
    if (l == 0) *invq_out = maxv * (1.f / 127.f);
}
#define NWROWS_W (N_EXP * D_OUT / 8)    // 512 blocks for W
// blocks [0, NWROWS_W): 8 W rows each; then NPAD/8 blocks of 8 x slots each
__global__ void k_convert(const float* __restrict__ x, const float* __restrict__ W) {
    const int bb = blockIdx.x;
    const int wrp = threadIdx.x >> 5;
    if (bb < NWROWS_W) {
        const int r = bb * 8 + wrp;
        const int e = r >> 9, co = r & 511;
        quant_row_warp(W + (size_t)r * D_IN,
                       g_w0c + (size_t)e * NCHUNK * D_OUT * 32,
                       g_w1c + (size_t)e * NCHUNK * D_OUT * 32,
                       (size_t)D_OUT * 32, co, co & 4, &g_invqw[r]);
    } else {
        const int p = (bb - NWROWS_W) * 8 + wrp;
        int e = 0;
        #pragma unroll
        for (int k = 1; k < N_EXP; ++k) e += (p >= g_off[k]);
        if (p >= g_end[e]) return;                 // pad slot
        const int src = g_perm[p];
        quant_row_warp(x + (size_t)src * D_IN,
                       g_x0c, g_x1c, (size_t)NPAD * 32, p, p & 4, &g_invqx[p]);
    }
}

// ---------------- grouped int8 GEMM: 6-stage pipeline, 2 CTAs/SM ------------
__global__ void __launch_bounds__(NTHREADS, 2) k_gemm(const float* __restrict__ b,
                                                      float* __restrict__ y) {
    const int e = g_tile_e[blockIdx.x];
    if (e < 0) return;
    const int row0    = g_tile_r[blockIdx.x];
    const int row_end = g_end[e];
    const int n0      = blockIdx.y * BN;

    extern __shared__ char smem[];
    __shared__ uint64_t mbar[NSTAGE];
    const uint32_t sb = smem_u32(smem);

    const int tid  = threadIdx.x;
    const int lane = tid & 31;
    const int warp = tid >> 5;
    const int warp_m = warp >> 1;       // 0..3 (32 rows)
    const int warp_n = warp & 1;        // 0..1 (32 cols)

    if (tid == 0) {
        #pragma unroll
        for (int s = 0; s < NSTAGE; ++s) MBARRIER_INIT(smem_u32(&mbar[s]), 1);
    }
    __syncthreads();

    auto issue = [&](int s, int ck) {
        const uint32_t mb = smem_u32(&mbar[s]);
        MBARRIER_EXPECT_TX(mb, STG);
        const uint32_t st = sb + s * STG;
        bulk_g2s(st,         g_x0c + ((size_t)ck * NPAD + row0) * 32, 4096, mb);
        bulk_g2s(st + 4096,  g_x1c + ((size_t)ck * NPAD + row0) * 32, 4096, mb);
        bulk_g2s(st + 8192,  g_w0c + ((size_t)(e * NCHUNK + ck) * D_OUT + n0) * 32, 2048, mb);
        bulk_g2s(st + 10240, g_w1c + ((size_t)(e * NCHUNK + ck) * D_OUT + n0) * 32, 2048, mb);
    };
    if (tid == 0) {
        #pragma unroll
        for (int k = 0; k < NSTAGE - 1; ++k) issue(k, k);
    }

    int accA[2][4][4], accC[2][4][4];
    #pragma unroll
    for (int i = 0; i < 2; ++i)
        #pragma unroll
        for (int j = 0; j < 4; ++j)
            #pragma unroll
            for (int k = 0; k < 4; ++k) { accA[i][j][k] = 0; accC[i][j][k] = 0; }

    const uint32_t a_row  = warp_m * 32 + (lane & 15);
    const uint32_t a_koff = (lane >> 4) * 16;
    const uint32_t aswz   = (a_row & 4) ? 16u : 0u;
    const uint32_t b_row  = warp_n * 32 + (lane & 7) + ((lane >> 4) & 1) * 8;
    const uint32_t b_koff = ((lane >> 3) & 1) * 16;
    const uint32_t bswz   = (b_row & 4) ? 16u : 0u;

    int stg = 0, ph = 0;                // consumer cursor
    for (int c = 0; c < NCHUNK; ++c) {
        MBARRIER_WAIT_PARITY(smem_u32(&mbar[stg]), ph);
        __syncthreads();                // all reads of the overwritten stage done
        if (tid == 0 && c + NSTAGE - 1 < NCHUNK) {
            int is = stg + NSTAGE - 1;
            if (is >= NSTAGE) is -= NSTAGE;
            issue(is, c + NSTAGE - 1);
        }

        const uint32_t st = sb + stg * STG;
        uint32_t a0[2][4], a1[2][4], w0[2][4], w1[2][4];
        #pragma unroll
        for (int mt = 0; mt < 2; ++mt) {
            const uint32_t ad = st + (a_row + mt * 16) * 32 + (a_koff ^ aswz);
            ldsm4(a0[mt], ad);
            ldsm4(a1[mt], ad + 4096);
        }
        #pragma unroll
        for (int nt2 = 0; nt2 < 2; ++nt2) {
            const uint32_t bd = st + 8192 + (b_row + nt2 * 16) * 32 + (b_koff ^ bswz);
            ldsm4(w0[nt2], bd);
            ldsm4(w1[nt2], bd + 2048);
        }
        #pragma unroll
        for (int mt = 0; mt < 2; ++mt)
            #pragma unroll
            for (int nt = 0; nt < 4; ++nt) {
                const uint32_t* p0 = &w0[nt >> 1][(nt & 1) * 2];
                const uint32_t* p1 = &w1[nt >> 1][(nt & 1) * 2];
                mma_s8(accA[mt][nt], a0[mt], p0[0], p0[1]);   // X0*W0
                mma_s8(accC[mt][nt], a0[mt], p1[0], p1[1]);   // X0*W1
                mma_s8(accC[mt][nt], a1[mt], p0[0], p0[1]);   // X1*W0
            }
        if (++stg == NSTAGE) { stg = 0; ph ^= 1; }
    }

    // epilogue: y = (accA + accC/128) * invqx[row]*invqw[col] + bias
    const float inv128 = 1.f / 128.f;
    const int ncol = n0 + warp_n * 32 + (lane & 3) * 2;
    float2 bias[4], fw[4];
    #pragma unroll
    for (int nt = 0; nt < 4; ++nt) {
        bias[nt] = *(const float2*)(b + (size_t)e * D_OUT + ncol + nt * 8);
        fw[nt]   = *(const float2*)(g_invqw + (size_t)e * D_OUT + ncol + nt * 8);
    }
    #pragma unroll
    for (int mt = 0; mt < 2; ++mt)
        #pragma unroll
        for (int half = 0; half < 2; ++half) {
            const int sr = row0 + warp_m * 32 + mt * 16 + (lane >> 2) + half * 8;
            if (sr < row_end) {
                const int g = g_perm[sr];
                const float fx = g_invqx[sr];
                float* yp = y + (size_t)g * D_OUT + ncol;
                #pragma unroll
                for (int nt = 0; nt < 4; ++nt) {
                    float v0 = (float)accA[mt][nt][half * 2 + 0]
                             + (float)accC[mt][nt][half * 2 + 0] * inv128;
                    float v1 = (float)accA[mt][nt][half * 2 + 1]
                             + (float)accC[mt][nt][half * 2 + 1] * inv128;
                    float2 v;
                    v.x = v0 * fx * fw[nt].x + bias[nt].x;
                    v.y = v1 * fx * fw[nt].y + bias[nt].y;
                    *(float2*)(yp + nt * 8) = v;
                }
            }
        }
}

// ---------------- entry -----------------------------------------------------
extern "C" void kernel_launch(void* const* d_in, const int* in_sizes, int n_in,
                              void* d_out, int out_size) {
    const float* x   = (const float*)d_in[0];
    const int*   idx = (const int*)  d_in[1];
    const float* W   = (const float*)d_in[2];
    const float* b   = (const float*)d_in[3];
    float*       y   = (float*)d_out;

    cudaFuncSetAttribute(k_gemm, cudaFuncAttributeMaxDynamicSharedMemorySize, SMEM_TOTAL);

    k_hist_scan<<<1, 1024>>>(idx);
    k_scatter<<<N_ROWS / 256, 256>>>(idx);
    k_convert<<<NWROWS_W + NPAD / 8, 256>>>(x, W);

    dim3 grid(MAX_TILES, D_OUT / BN);
    k_gemm<<<grid, NTHREADS, SMEM_TOTAL>>>(b, y);
}